// round 8
// baseline (speedup 1.0000x reference)
#include <cuda_runtime.h>
#include <cuda_bf16.h>
#include <math.h>

#define NQ      32
#define DIM     128
#define TOPK    10
#define NBLK    296                // one wave at 2 blocks/SM on 148 SMs
#define TPB     192                // 128 consumer threads + 64 producer threads
#define SLOTS   64                 // candidates per (query, block) = 32 threads * 2
#define MCAND   (NBLK * SLOTS)     // 18944 per query
#define NRES    32                 // exactly-rescored candidates per query
#define NEG_INF (-3.402823466e38f)
#define MAGIC   12582912.0f        // 1.5 * 2^23
#define CSCALE  (127.0f / 6.6f)
#define CSTRIDE 36                 // ints per c8 row (144B: LDS.128-aligned, conflict-free)

// ---- static device scratch ----
__device__ float g_qn[NQ * DIM];
__device__ int   g_q8[NQ * 32];
__device__ float g_psc[NBLK * NQ * SLOTS];
__device__ int   g_pix[NBLK * NQ * SLOTS];

// ============================================================
// K1: one warp per query — normalize + int8 quantize/pack
// ============================================================
__global__ void k1_prep(const float* __restrict__ q) {
    const int w = threadIdx.x >> 5;   // query
    const int l = threadIdx.x & 31;   // float4 lane
    const float4 v = __ldg(&((const float4*)q)[w * 32 + l]);
    float ss = v.x * v.x + v.y * v.y + v.z * v.z + v.w * v.w;
    #pragma unroll
    for (int o = 16; o > 0; o >>= 1) ss += __shfl_xor_sync(0xffffffffu, ss, o);
    const float inv = 1.f / fmaxf(sqrtf(ss), 1e-12f);
    float4 n = make_float4(v.x * inv, v.y * inv, v.z * inv, v.w * inv);
    ((float4*)g_qn)[w * 32 + l] = n;
    float ma = fmaxf(fmaxf(fabsf(n.x), fabsf(n.y)), fmaxf(fabsf(n.z), fabsf(n.w)));
    #pragma unroll
    for (int o = 16; o > 0; o >>= 1) ma = fmaxf(ma, __shfl_xor_sync(0xffffffffu, ma, o));
    const float sc = 127.f / fmaxf(ma, 1e-12f);
    int b0 = __float_as_int(fminf(fmaxf(n.x * sc, -127.f), 127.f) + MAGIC);
    int b1 = __float_as_int(fminf(fmaxf(n.y * sc, -127.f), 127.f) + MAGIC);
    int b2 = __float_as_int(fminf(fmaxf(n.z * sc, -127.f), 127.f) + MAGIC);
    int b3 = __float_as_int(fminf(fmaxf(n.w * sc, -127.f), 127.f) + MAGIC);
    g_q8[w * 32 + l] = __byte_perm(__byte_perm(b0, b1, 0x0040),
                                   __byte_perm(b2, b3, 0x0040), 0x5410);
}

// ============================================================
// K2: warp-specialized double-buffered int8 dp4a scan
//   warps 0-3: consumers (4 rows x 8 queries register tile, top-2/query)
//   warps 4-5: producers (LDG -> quantize -> STS next tile + inline row norms)
// ============================================================
__global__ void __launch_bounds__(TPB, 2)
k2_scan(const float* __restrict__ corpus, int N, int rpb) {
    __shared__ __align__(16) int   c8[2][128 * CSTRIDE]; // unswizzled, 144B row stride
    __shared__ __align__(16) int   q8s[NQ * 32];         // XOR-swizzled on q>>3
    __shared__ float rinv[2][128];

    const int tid = threadIdx.x;
    const int row0   = blockIdx.x * rpb;
    const int rowEnd = min(row0 + rpb, N);
    const int T = (rowEnd - row0 + 127) >> 7;

    // stage queries (swizzle: phys_group = gp ^ (q>>3))
    for (int i = tid; i < NQ * 32; i += TPB) {
        int q = i >> 5, k4 = i & 31;
        int gp = k4 >> 2, m = k4 & 3;
        int phys = (((gp ^ (q >> 3)) & 7) << 2) | m;
        q8s[q * 32 + phys] = g_q8[i];
    }

    const float4* gc = (const float4*)corpus;
    const bool is_prod = tid >= 128;

    // ---------------- producer staging (lambda-style via macro-free inline) ----
    // producer warp p in {0,1}; iteration i in [0,64): row = 2*i+p; lane = float4 idx
    const int pw   = (tid - 128) >> 5;   // producer warp id (garbage for consumers)
    const int lane = tid & 31;

    // consumer ids
    const int qg = tid & 3;      // query group
    const int rg = tid >> 2;     // row group (consumers only, tid<128)

    float b1[8], b2[8]; int x1[8], x2[8];
    #pragma unroll
    for (int j = 0; j < 8; j++) { b1[j] = NEG_INF; b2[j] = NEG_INF; x1[j] = 0; x2[j] = 0; }

    // -------- prologue: stage tile 0 into buffer 0 --------
    if (is_prod) {
        #pragma unroll
        for (int b = 0; b < 4; b++) {
            float4 fv[16];
            #pragma unroll
            for (int k = 0; k < 16; k++) {
                int row = ((b * 16 + k) << 1) + pw;
                fv[k] = (row0 + row < rowEnd) ? __ldg(&gc[(size_t)(row0 + row) * 32 + lane])
                                              : make_float4(0.f, 0.f, 0.f, 0.f);
            }
            #pragma unroll
            for (int k = 0; k < 16; k++) {
                int row = ((b * 16 + k) << 1) + pw;
                int i0 = __float_as_int(fmaf(fv[k].x, CSCALE, MAGIC));
                int i1 = __float_as_int(fmaf(fv[k].y, CSCALE, MAGIC));
                int i2 = __float_as_int(fmaf(fv[k].z, CSCALE, MAGIC));
                int i3 = __float_as_int(fmaf(fv[k].w, CSCALE, MAGIC));
                int pk = __byte_perm(__byte_perm(i0, i1, 0x0040),
                                     __byte_perm(i2, i3, 0x0040), 0x5410);
                c8[0][row * CSTRIDE + lane] = pk;
                int nsq = __dp4a(pk, pk, 0);
                nsq = __reduce_add_sync(0xffffffffu, nsq);
                if (lane == 0) rinv[0][row] = rsqrtf((float)max(nsq, 1));
            }
        }
    }
    __syncthreads();

    // -------- main loop: consumers compute tile t, producers stage tile t+1 --------
    for (int t = 0; t < T; t++) {
        const int cur = t & 1;
        if (is_prod) {
            if (t + 1 < T) {
                const int tb = row0 + ((t + 1) << 7);
                const int nxt = cur ^ 1;
                #pragma unroll
                for (int b = 0; b < 4; b++) {
                    float4 fv[16];
                    #pragma unroll
                    for (int k = 0; k < 16; k++) {
                        int row = ((b * 16 + k) << 1) + pw;
                        fv[k] = (tb + row < rowEnd) ? __ldg(&gc[(size_t)(tb + row) * 32 + lane])
                                                    : make_float4(0.f, 0.f, 0.f, 0.f);
                    }
                    #pragma unroll
                    for (int k = 0; k < 16; k++) {
                        int row = ((b * 16 + k) << 1) + pw;
                        int i0 = __float_as_int(fmaf(fv[k].x, CSCALE, MAGIC));
                        int i1 = __float_as_int(fmaf(fv[k].y, CSCALE, MAGIC));
                        int i2 = __float_as_int(fmaf(fv[k].z, CSCALE, MAGIC));
                        int i3 = __float_as_int(fmaf(fv[k].w, CSCALE, MAGIC));
                        int pk = __byte_perm(__byte_perm(i0, i1, 0x0040),
                                             __byte_perm(i2, i3, 0x0040), 0x5410);
                        c8[nxt][row * CSTRIDE + lane] = pk;
                        int nsq = __dp4a(pk, pk, 0);
                        nsq = __reduce_add_sync(0xffffffffu, nsq);
                        if (lane == 0) rinv[nxt][row] = rsqrtf((float)max(nsq, 1));
                    }
                }
            }
        } else {
            const int tb = row0 + (t << 7);
            const int* cb = c8[cur];
            int acc[4][8];
            #pragma unroll
            for (int i = 0; i < 4; i++)
                #pragma unroll
                for (int j = 0; j < 8; j++) acc[i][j] = 0;

            #pragma unroll
            for (int g = 0; g < 8; g++) {
                int4 cv[4];
                #pragma unroll
                for (int i = 0; i < 4; i++)
                    cv[i] = *(const int4*)&cb[(rg + 32 * i) * CSTRIDE + (g << 2)];
                #pragma unroll
                for (int j = 0; j < 8; j++) {
                    const int q = qg * 8 + j;
                    const int4 qv = *(const int4*)&q8s[q * 32 + (((g ^ qg) & 7) << 2)];
                    #pragma unroll
                    for (int i = 0; i < 4; i++) {
                        acc[i][j] = __dp4a(cv[i].x, qv.x, acc[i][j]);
                        acc[i][j] = __dp4a(cv[i].y, qv.y, acc[i][j]);
                        acc[i][j] = __dp4a(cv[i].z, qv.z, acc[i][j]);
                        acc[i][j] = __dp4a(cv[i].w, qv.w, acc[i][j]);
                    }
                }
            }
            #pragma unroll
            for (int i = 0; i < 4; i++) {
                const int row = tb + rg + 32 * i;
                if (row < rowEnd) {
                    const float ri = rinv[cur][rg + 32 * i];
                    #pragma unroll
                    for (int j = 0; j < 8; j++) {
                        float s = (float)acc[i][j] * ri;
                        if (s > b1[j]) { b2[j] = b1[j]; x2[j] = x1[j]; b1[j] = s; x1[j] = row; }
                        else if (s > b2[j]) { b2[j] = s; x2[j] = row; }
                    }
                }
            }
        }
        __syncthreads();
    }

    // consumers publish candidates
    if (!is_prod) {
        #pragma unroll
        for (int j = 0; j < 8; j++) {
            int q = qg * 8 + j;
            int base = (blockIdx.x * NQ + q) * SLOTS + rg * 2;
            g_psc[base]     = b1[j];  g_psc[base + 1] = b2[j];
            g_pix[base]     = x1[j];  g_pix[base + 1] = x2[j];
        }
    }
}

// ============================================================
// K3: per-query merge + exact fp32 rescore + jax-tie-break top-10
// ============================================================
__global__ void __launch_bounds__(256, 1)
k3_merge(const float* __restrict__ corpus, float* __restrict__ out, int N) {
    __shared__ float cs[1024];
    __shared__ int   ci[1024];
    __shared__ __align__(16) float qn_s[DIM];
    __shared__ float red_s[8];
    __shared__ int   red_p[8];
    __shared__ float rs[NRES];
    __shared__ int   rix[NRES];

    const int q = blockIdx.x;
    const int t = threadIdx.x;

    if (t < DIM) qn_s[t] = g_qn[q * DIM + t];

    float b[4]  = {NEG_INF, NEG_INF, NEG_INF, NEG_INF};
    int   bx[4] = {0, 0, 0, 0};
    for (int c = t; c < MCAND; c += 256) {
        int blk = c >> 6, slot = c & 63;
        int addr = (blk * NQ + q) * SLOTS + slot;
        float s = g_psc[addr];
        if (s > b[3]) {
            int id = g_pix[addr];
            if (s > b[0]) { b[3]=b[2]; bx[3]=bx[2]; b[2]=b[1]; bx[2]=bx[1]; b[1]=b[0]; bx[1]=bx[0]; b[0]=s; bx[0]=id; }
            else if (s > b[1]) { b[3]=b[2]; bx[3]=bx[2]; b[2]=b[1]; bx[2]=bx[1]; b[1]=s; bx[1]=id; }
            else if (s > b[2]) { b[3]=b[2]; bx[3]=bx[2]; b[2]=s; bx[2]=id; }
            else               { b[3]=s; bx[3]=id; }
        }
    }
    #pragma unroll
    for (int k = 0; k < 4; k++) { cs[t * 4 + k] = b[k]; ci[t * 4 + k] = bx[k]; }
    __syncthreads();

    for (int r = 0; r < NRES; r++) {
        float mv = NEG_INF; int mp = 0;
        #pragma unroll
        for (int k = 0; k < 4; k++) {
            float v = cs[t * 4 + k];
            if (v > mv) { mv = v; mp = t * 4 + k; }
        }
        #pragma unroll
        for (int o = 16; o > 0; o >>= 1) {
            float ov = __shfl_down_sync(0xffffffffu, mv, o);
            int   op = __shfl_down_sync(0xffffffffu, mp, o);
            if (ov > mv) { mv = ov; mp = op; }
        }
        if ((t & 31) == 0) { red_s[t >> 5] = mv; red_p[t >> 5] = mp; }
        __syncthreads();
        if (t == 0) {
            float wv = red_s[0]; int wp = red_p[0];
            #pragma unroll
            for (int w = 1; w < 8; w++)
                if (red_s[w] > wv) { wv = red_s[w]; wp = red_p[w]; }
            rix[r] = ci[wp];
            cs[wp] = NEG_INF;
        }
        __syncthreads();
    }

    const int w = t >> 5, l = t & 31;
    for (int c = w; c < NRES; c += 8) {
        int idx = rix[c];
        const float4 cv = __ldg(&((const float4*)corpus)[(size_t)idx * 32 + l]);
        float4 qv = *(const float4*)&qn_s[l * 4];
        float dot = cv.x * qv.x + cv.y * qv.y + cv.z * qv.z + cv.w * qv.w;
        float n2  = cv.x * cv.x + cv.y * cv.y + cv.z * cv.z + cv.w * cv.w;
        #pragma unroll
        for (int o = 16; o > 0; o >>= 1) {
            dot += __shfl_down_sync(0xffffffffu, dot, o);
            n2  += __shfl_down_sync(0xffffffffu, n2,  o);
        }
        if (l == 0) rs[c] = dot / fmaxf(sqrtf(n2), 1e-12f);
    }
    __syncthreads();

    if (t < NRES) {
        float s = rs[t]; int id = rix[t];
        int rank = 0;
        for (int jj = 0; jj < NRES; jj++) {
            float so = rs[jj]; int io = rix[jj];
            if (so > s || (so == s && io < id)) rank++;
        }
        if (rank < TOPK) {
            out[q * TOPK + rank]             = s;
            out[NQ * TOPK + q * TOPK + rank] = (float)id;
        }
    }
}

extern "C" void kernel_launch(void* const* d_in, const int* in_sizes, int n_in,
                              void* d_out, int out_size) {
    const float* queries = (const float*)d_in[0];
    const float* corpus  = (const float*)d_in[1];
    int N   = in_sizes[1] / DIM;
    int rpb = (N + NBLK - 1) / NBLK;
    k1_prep<<<1, 1024>>>(queries);
    k2_scan<<<NBLK, TPB>>>(corpus, N, rpb);
    k3_merge<<<NQ, 256>>>(corpus, (float*)d_out, N);
}

// round 10
// speedup vs baseline: 1.5365x; 1.5365x over previous
#include <cuda_runtime.h>
#include <cuda_bf16.h>
#include <math.h>

#define NQ      32
#define DIM     128
#define TOPK    10
#define NBLK    1184               // 8 CTAs/SM resident in 2 waves at 4/SM
#define TPB     128
#define SLOTS   32                 // per (query, block): 16 threads * top-2
#define MCAND   (NBLK * SLOTS)     // 37888 per query
#define NRES    32
#define NEG_INF (-3.402823466e38f)
#define MAGIC   12582912.0f        // 1.5 * 2^23
#define CSCALE  (127.0f / 6.6f)
#define CSTRIDE 36                 // ints per c8 row: 144B, conflict-free LDS.128

// ---- static device scratch ----
__device__ float g_qn[NQ * DIM];
__device__ int   g_q8[NQ * 32];
__device__ float g_psc[NBLK * NQ * SLOTS];
__device__ int   g_pix[NBLK * NQ * SLOTS];

// ============================================================
// K1: one warp per query — normalize + int8 quantize/pack
// ============================================================
__global__ void k1_prep(const float* __restrict__ q) {
    const int w = threadIdx.x >> 5;
    const int l = threadIdx.x & 31;
    const float4 v = __ldg(&((const float4*)q)[w * 32 + l]);
    float ss = v.x * v.x + v.y * v.y + v.z * v.z + v.w * v.w;
    #pragma unroll
    for (int o = 16; o > 0; o >>= 1) ss += __shfl_xor_sync(0xffffffffu, ss, o);
    const float inv = 1.f / fmaxf(sqrtf(ss), 1e-12f);
    float4 n = make_float4(v.x * inv, v.y * inv, v.z * inv, v.w * inv);
    ((float4*)g_qn)[w * 32 + l] = n;
    float ma = fmaxf(fmaxf(fabsf(n.x), fabsf(n.y)), fmaxf(fabsf(n.z), fabsf(n.w)));
    #pragma unroll
    for (int o = 16; o > 0; o >>= 1) ma = fmaxf(ma, __shfl_xor_sync(0xffffffffu, ma, o));
    const float sc = 127.f / fmaxf(ma, 1e-12f);
    int b0 = __float_as_int(fminf(fmaxf(n.x * sc, -127.f), 127.f) + MAGIC);
    int b1 = __float_as_int(fminf(fmaxf(n.y * sc, -127.f), 127.f) + MAGIC);
    int b2 = __float_as_int(fminf(fmaxf(n.z * sc, -127.f), 127.f) + MAGIC);
    int b3 = __float_as_int(fminf(fmaxf(n.w * sc, -127.f), 127.f) + MAGIC);
    g_q8[w * 32 + l] = __byte_perm(__byte_perm(b0, b1, 0x0040),
                                   __byte_perm(b2, b3, 0x0040), 0x5410);
}

// ============================================================
// K2: int8 dp4a scan, 8 rows x 4 queries register tile,
//     MLP-8 batched stage with fused warp-reduce row norms
// ============================================================
__global__ void __launch_bounds__(TPB, 4)
k2_scan(const float* __restrict__ corpus, int N, int rpb) {
    __shared__ __align__(16) int   c8 [128 * CSTRIDE];  // 18.4 KB
    __shared__ __align__(16) int   q8s[NQ * 32];        // swizzled on q>>2
    __shared__ float rinv[128];

    const int tid  = threadIdx.x;
    const int lane = tid & 31;
    const int wrp  = tid >> 5;
    const int qg   = tid & 7;     // 8 query groups of 4
    const int rg   = tid >> 3;    // [0,16): rows rg + 16*i
    const int row0   = blockIdx.x * rpb;
    const int rowEnd = min(row0 + rpb, N);

    // stage queries: phys 16B-group = gp ^ (q>>2)
    for (int i = tid; i < NQ * 32; i += TPB) {
        int q = i >> 5, k4 = i & 31;
        int gp = k4 >> 2, m = k4 & 3;
        int phys = (((gp ^ (q >> 2)) & 7) << 2) | m;
        q8s[q * 32 + phys] = g_q8[i];
    }

    float b1[4], b2[4]; int x1[4], x2[4];
    #pragma unroll
    for (int j = 0; j < 4; j++) { b1[j] = NEG_INF; b2[j] = NEG_INF; x1[j] = 0; x2[j] = 0; }

    const float4* gc = (const float4*)corpus;

    for (int tb = row0; tb < rowEnd; tb += 128) {
        __syncthreads();    // previous tile's readers done
        // ---- stage: 4 batches of 8 LDG.128, fused norm (warp w owns row 4*it+w) ----
        #pragma unroll
        for (int b = 0; b < 4; b++) {
            float4 fv[8];
            #pragma unroll
            for (int k = 0; k < 8; k++) {
                int r = ((b * 8 + k) << 2) + wrp;        // local row
                fv[k] = (tb + r < rowEnd) ? __ldg(&gc[(size_t)(tb + r) * 32 + lane])
                                          : make_float4(0.f, 0.f, 0.f, 0.f);
            }
            #pragma unroll
            for (int k = 0; k < 8; k++) {
                int r = ((b * 8 + k) << 2) + wrp;
                int i0 = __float_as_int(fmaf(fv[k].x, CSCALE, MAGIC));
                int i1 = __float_as_int(fmaf(fv[k].y, CSCALE, MAGIC));
                int i2 = __float_as_int(fmaf(fv[k].z, CSCALE, MAGIC));
                int i3 = __float_as_int(fmaf(fv[k].w, CSCALE, MAGIC));
                int pk = __byte_perm(__byte_perm(i0, i1, 0x0040),
                                     __byte_perm(i2, i3, 0x0040), 0x5410);
                c8[r * CSTRIDE + lane] = pk;
                int nsq = __reduce_add_sync(0xffffffffu, __dp4a(pk, pk, 0));
                if (lane == 0) rinv[r] = rsqrtf((float)max(nsq, 1));
            }
        }
        __syncthreads();

        // ---- compute: 8 rows x 4 queries per thread ----
        int acc[8][4];
        #pragma unroll
        for (int i = 0; i < 8; i++)
            #pragma unroll
            for (int j = 0; j < 4; j++) acc[i][j] = 0;

        #pragma unroll
        for (int g = 0; g < 8; g++) {
            int4 cv[8];
            #pragma unroll
            for (int i = 0; i < 8; i++)
                cv[i] = *(const int4*)&c8[(rg + 16 * i) * CSTRIDE + (g << 2)];
            #pragma unroll
            for (int j = 0; j < 4; j++) {
                const int q = qg * 4 + j;
                const int4 qv = *(const int4*)&q8s[q * 32 + (((g ^ qg) & 7) << 2)];
                #pragma unroll
                for (int i = 0; i < 8; i++) {
                    acc[i][j] = __dp4a(cv[i].x, qv.x, acc[i][j]);
                    acc[i][j] = __dp4a(cv[i].y, qv.y, acc[i][j]);
                    acc[i][j] = __dp4a(cv[i].z, qv.z, acc[i][j]);
                    acc[i][j] = __dp4a(cv[i].w, qv.w, acc[i][j]);
                }
            }
        }

        // ---- top-2 per (thread, query) ----
        #pragma unroll
        for (int i = 0; i < 8; i++) {
            const int row = tb + rg + 16 * i;
            if (row < rowEnd) {
                const float ri = rinv[rg + 16 * i];
                #pragma unroll
                for (int j = 0; j < 4; j++) {
                    float s = (float)acc[i][j] * ri;
                    if (s > b1[j]) { b2[j] = b1[j]; x2[j] = x1[j]; b1[j] = s; x1[j] = row; }
                    else if (s > b2[j]) { b2[j] = s; x2[j] = row; }
                }
            }
        }
    }

    // ---- publish candidates ----
    #pragma unroll
    for (int j = 0; j < 4; j++) {
        int q = qg * 4 + j;
        int base = (blockIdx.x * NQ + q) * SLOTS + rg * 2;
        g_psc[base]     = b1[j];  g_psc[base + 1] = b2[j];
        g_pix[base]     = x1[j];  g_pix[base + 1] = x2[j];
    }
}

// ============================================================
// K3: per-query merge + exact fp32 rescore + jax-tie-break top-10
// ============================================================
__global__ void __launch_bounds__(256, 1)
k3_merge(const float* __restrict__ corpus, float* __restrict__ out, int N) {
    __shared__ float cs[1024];
    __shared__ int   ci[1024];
    __shared__ __align__(16) float qn_s[DIM];
    __shared__ float red_s[8];
    __shared__ int   red_p[8];
    __shared__ float rs[NRES];
    __shared__ int   rix[NRES];

    const int q = blockIdx.x;
    const int t = threadIdx.x;

    if (t < DIM) qn_s[t] = g_qn[q * DIM + t];

    float b[4]  = {NEG_INF, NEG_INF, NEG_INF, NEG_INF};
    int   bx[4] = {0, 0, 0, 0};
    for (int c = t; c < MCAND; c += 256) {
        int blk = c >> 5, slot = c & 31;
        int addr = (blk * NQ + q) * SLOTS + slot;
        float s = g_psc[addr];
        if (s > b[3]) {
            int id = g_pix[addr];
            if (s > b[0]) { b[3]=b[2]; bx[3]=bx[2]; b[2]=b[1]; bx[2]=bx[1]; b[1]=b[0]; bx[1]=bx[0]; b[0]=s; bx[0]=id; }
            else if (s > b[1]) { b[3]=b[2]; bx[3]=bx[2]; b[2]=b[1]; bx[2]=bx[1]; b[1]=s; bx[1]=id; }
            else if (s > b[2]) { b[3]=b[2]; bx[3]=bx[2]; b[2]=s; bx[2]=id; }
            else               { b[3]=s; bx[3]=id; }
        }
    }
    #pragma unroll
    for (int k = 0; k < 4; k++) { cs[t * 4 + k] = b[k]; ci[t * 4 + k] = bx[k]; }
    __syncthreads();

    for (int r = 0; r < NRES; r++) {
        float mv = NEG_INF; int mp = 0;
        #pragma unroll
        for (int k = 0; k < 4; k++) {
            float v = cs[t * 4 + k];
            if (v > mv) { mv = v; mp = t * 4 + k; }
        }
        #pragma unroll
        for (int o = 16; o > 0; o >>= 1) {
            float ov = __shfl_down_sync(0xffffffffu, mv, o);
            int   op = __shfl_down_sync(0xffffffffu, mp, o);
            if (ov > mv) { mv = ov; mp = op; }
        }
        if ((t & 31) == 0) { red_s[t >> 5] = mv; red_p[t >> 5] = mp; }
        __syncthreads();
        if (t == 0) {
            float wv = red_s[0]; int wp = red_p[0];
            #pragma unroll
            for (int w = 1; w < 8; w++)
                if (red_s[w] > wv) { wv = red_s[w]; wp = red_p[w]; }
            rix[r] = ci[wp];
            cs[wp] = NEG_INF;
        }
        __syncthreads();
    }

    const int w = t >> 5, l = t & 31;
    for (int c = w; c < NRES; c += 8) {
        int idx = rix[c];
        const float4 cv = __ldg(&((const float4*)corpus)[(size_t)idx * 32 + l]);
        float4 qv = *(const float4*)&qn_s[l * 4];
        float dot = cv.x * qv.x + cv.y * qv.y + cv.z * qv.z + cv.w * qv.w;
        float n2  = cv.x * cv.x + cv.y * cv.y + cv.z * cv.z + cv.w * cv.w;
        #pragma unroll
        for (int o = 16; o > 0; o >>= 1) {
            dot += __shfl_down_sync(0xffffffffu, dot, o);
            n2  += __shfl_down_sync(0xffffffffu, n2,  o);
        }
        if (l == 0) rs[c] = dot / fmaxf(sqrtf(n2), 1e-12f);
    }
    __syncthreads();

    if (t < NRES) {
        float s = rs[t]; int id = rix[t];
        int rank = 0;
        for (int jj = 0; jj < NRES; jj++) {
            float so = rs[jj]; int io = rix[jj];
            if (so > s || (so == s && io < id)) rank++;
        }
        if (rank < TOPK) {
            out[q * TOPK + rank]             = s;
            out[NQ * TOPK + q * TOPK + rank] = (float)id;
        }
    }
}

extern "C" void kernel_launch(void* const* d_in, const int* in_sizes, int n_in,
                              void* d_out, int out_size) {
    const float* queries = (const float*)d_in[0];
    const float* corpus  = (const float*)d_in[1];
    int N   = in_sizes[1] / DIM;
    int rpb = (N + NBLK - 1) / NBLK;
    k1_prep<<<1, 1024>>>(queries);
    k2_scan<<<NBLK, TPB>>>(corpus, N, rpb);
    k3_merge<<<NQ, 256>>>(corpus, (float*)d_out, N);
}

// round 14
// speedup vs baseline: 1.7766x; 1.1563x over previous
#include <cuda_runtime.h>
#include <cuda_bf16.h>
#include <math.h>
#include <stdint.h>

#define NQ      32
#define DIM     128
#define TOPK    10
#define NBLK    296                // 2 CTAs/SM, one wave
#define TPB     256                // 8 warps; warp w owns rows [16w,16w+16) of each tile
#define SLOTS   256                // entries per (query, block)
#define MCAND   (NBLK * SLOTS)     // 75776 per query
#define NRES    32
#define NEG_INF (-3.402823466e38f)

// ---- static device scratch ----
__device__ float g_qn[NQ * DIM];
__device__ float g_psc[NBLK * NQ * SLOTS];
__device__ int   g_pix[NBLK * NQ * SLOTS];

__device__ __forceinline__ uint32_t bf2(float lo, float hi) {
    uint32_t d;
    asm("cvt.rn.bf16x2.f32 %0, %1, %2;" : "=r"(d) : "f"(hi), "f"(lo));
    return d;
}
__device__ __forceinline__ void mma16816(float* c, uint32_t a0, uint32_t a1,
                                         uint32_t a2, uint32_t a3,
                                         uint32_t b0, uint32_t b1) {
    asm volatile(
        "mma.sync.aligned.m16n8k16.row.col.f32.bf16.bf16.f32 "
        "{%0,%1,%2,%3}, {%4,%5,%6,%7}, {%8,%9}, {%0,%1,%2,%3};"
        : "+f"(c[0]), "+f"(c[1]), "+f"(c[2]), "+f"(c[3])
        : "r"(a0), "r"(a1), "r"(a2), "r"(a3), "r"(b0), "r"(b1));
}

// ============================================================
// K1: one warp per query — L2-normalize into g_qn
// ============================================================
__global__ void k1_prep(const float* __restrict__ q) {
    const int w = threadIdx.x >> 5;
    const int l = threadIdx.x & 31;
    const float4 v = __ldg(&((const float4*)q)[w * 32 + l]);
    float ss = v.x * v.x + v.y * v.y + v.z * v.z + v.w * v.w;
    #pragma unroll
    for (int o = 16; o > 0; o >>= 1) ss += __shfl_xor_sync(0xffffffffu, ss, o);
    const float inv = 1.f / fmaxf(sqrtf(ss), 1e-12f);
    ((float4*)g_qn)[w * 32 + l] = make_float4(v.x * inv, v.y * inv, v.z * inv, v.w * inv);
}

// ============================================================
// K2: warp-level bf16 mma.sync scan (no smem A, no hot-loop barrier)
//   D[16 rows x 32 queries] per warp per tile; A fragments straight from gmem.
// ============================================================
__global__ void __launch_bounds__(TPB, 2)
k2_scan(const float* __restrict__ corpus, int N, int rpb) {
    // smQ word(k2, n) at k2*32 + ((n + 8*(k2&3)) & 31); k2 = k/2 in [0,64)
    __shared__ __align__(16) uint32_t smQ[64 * 32];

    const int t    = threadIdx.x;
    const int wrp  = t >> 5;
    const int lane = t & 31;
    const int g    = lane >> 2;     // groupID
    const int tig  = lane & 3;      // threadID_in_group
    const int row0   = blockIdx.x * rpb;
    const int rowEnd = min(row0 + rpb, N);
    const int T = (rowEnd > row0) ? ((rowEnd - row0 + 127) >> 7) : 0;

    // stage B: queries as bf16x2, swizzled
    for (int i = t; i < 64 * 32; i += TPB) {
        int k2 = i >> 5, n = i & 31;
        uint32_t w2 = bf2(g_qn[n * DIM + 2 * k2], g_qn[n * DIM + 2 * k2 + 1]);
        smQ[k2 * 32 + ((n + ((k2 & 3) << 3)) & 31)] = w2;
    }
    __syncthreads();

    // preload this thread's 64 B-fragment regs? kept in smem; compute LDS addrs base
    // b0(kt,nb): word (kt*8+tig,  nb*8+g) ; b1: word (kt*8+tig+4, nb*8+g)
    uint32_t baddr[8][2];
    #pragma unroll
    for (int kt = 0; kt < 8; kt++) {
        int k2a = kt * 8 + tig, k2b = k2a + 4;
        baddr[kt][0] = (uint32_t)(k2a * 32);
        baddr[kt][1] = (uint32_t)(k2b * 32);
    }
    const uint32_t nrot = (uint32_t)(g + (tig << 3));   // (n + 8*(k2&3)) with n=nb*8+g, k2&3=tig

    float m1[16], m2[16];
    #pragma unroll
    for (int s = 0; s < 16; s++) { m1[s] = NEG_INF; m2[s] = NEG_INF; }

    const float2* gc2 = (const float2*)corpus;

    for (int tl = 0; tl < T; tl++) {
        const int rA = row0 + (tl << 7) + wrp * 16 + g;   // row g
        const int rB = rA + 8;                            // row g+8
        const bool vA = rA < rowEnd, vB = rB < rowEnd;
        const float2* pA = gc2 + (size_t)rA * 64 + tig;
        const float2* pB = gc2 + (size_t)rB * 64 + tig;

        float acc[4][4];
        #pragma unroll
        for (int nb = 0; nb < 4; nb++)
            #pragma unroll
            for (int ci = 0; ci < 4; ci++) acc[nb][ci] = 0.f;

        float ss0 = 0.f, ss1 = 0.f;
        #pragma unroll
        for (int kt = 0; kt < 8; kt++) {
            const float2 z = make_float2(0.f, 0.f);
            float2 faL = vA ? __ldg(pA + kt * 8)     : z;   // row g,  k = 16kt+2tig
            float2 faH = vA ? __ldg(pA + kt * 8 + 4) : z;   // row g,  k + 8
            float2 fbL = vB ? __ldg(pB + kt * 8)     : z;   // row g+8
            float2 fbH = vB ? __ldg(pB + kt * 8 + 4) : z;
            ss0 += faL.x * faL.x + faL.y * faL.y + faH.x * faH.x + faH.y * faH.y;
            ss1 += fbL.x * fbL.x + fbL.y * fbL.y + fbH.x * fbH.x + fbH.y * fbH.y;
            uint32_t a0 = bf2(faL.x, faL.y);
            uint32_t a1 = bf2(fbL.x, fbL.y);
            uint32_t a2 = bf2(faH.x, faH.y);
            uint32_t a3 = bf2(fbH.x, fbH.y);
            #pragma unroll
            for (int nb = 0; nb < 4; nb++) {
                uint32_t col = (uint32_t)((nrot + nb * 8) & 31);
                uint32_t b0 = smQ[baddr[kt][0] + col];
                uint32_t b1 = smQ[baddr[kt][1] + col];
                mma16816(acc[nb], a0, a1, a2, a3, b0, b1);
            }
        }
        // row norms: reduce over the 4 lanes of the quad
        ss0 += __shfl_xor_sync(0xffffffffu, ss0, 1);
        ss0 += __shfl_xor_sync(0xffffffffu, ss0, 2);
        ss1 += __shfl_xor_sync(0xffffffffu, ss1, 1);
        ss1 += __shfl_xor_sync(0xffffffffu, ss1, 2);
        const float ri0 = rsqrtf(fmaxf(ss0, 1e-24f));
        const float ri1 = rsqrtf(fmaxf(ss1, 1e-24f));
        const uint32_t tlb = (uint32_t)tl;   // tile id in low 8 mantissa bits
        #pragma unroll
        for (int nb = 0; nb < 4; nb++) {
            #pragma unroll
            for (int ci = 0; ci < 4; ci++) {
                const float ri = (ci >= 2) ? ri1 : ri0;
                float sv = acc[nb][ci] * ri;
                sv = __uint_as_float((__float_as_uint(sv) & ~0xFFu) | tlb);
                const int s = nb * 4 + ci;
                if (sv > m1[s]) { m2[s] = m1[s]; m1[s] = sv; }
                else if (sv > m2[s]) { m2[s] = sv; }
            }
        }
    }

    // publish: per query, entry e = wrp*32 + g*4 + rowhalf*2 + {0,1}
    #pragma unroll
    for (int s = 0; s < 16; s++) {
        const int nb = s >> 2, ci = s & 3;
        const int q  = nb * 8 + tig * 2 + (ci & 1);
        const int rh = ci >> 1;
        const int e  = wrp * 32 + g * 4 + rh * 2;
        const int base = (blockIdx.x * NQ + q) * SLOTS + e;
        #pragma unroll
        for (int k = 0; k < 2; k++) {
            const float sv = k ? m2[s] : m1[s];
            const uint32_t bits = __float_as_uint(sv);
            const int row = row0 + (int)(bits & 0xFFu) * 128 + wrp * 16 + g + rh * 8;
            g_psc[base + k] = sv;
            g_pix[base + k] = row;
        }
    }
}

// ============================================================
// K3: per-query merge + exact fp32 rescore + jax-tie-break top-10
// ============================================================
__global__ void __launch_bounds__(256, 1)
k3_merge(const float* __restrict__ corpus, float* __restrict__ out, int N) {
    __shared__ float cs[1024];
    __shared__ int   ci[1024];
    __shared__ __align__(16) float qn_s[DIM];
    __shared__ float red_s[8];
    __shared__ int   red_p[8];
    __shared__ float rs[NRES];
    __shared__ int   rix[NRES];

    const int q = blockIdx.x;
    const int t = threadIdx.x;

    if (t < DIM) qn_s[t] = g_qn[q * DIM + t];

    float b[4]  = {NEG_INF, NEG_INF, NEG_INF, NEG_INF};
    int   bx[4] = {0, 0, 0, 0};
    for (int c = t; c < MCAND; c += 256) {
        int blk = c >> 8, slot = c & 255;
        int addr = (blk * NQ + q) * SLOTS + slot;
        float s = g_psc[addr];
        if (s > b[3]) {
            int id = g_pix[addr];
            if (s > b[0]) { b[3]=b[2]; bx[3]=bx[2]; b[2]=b[1]; bx[2]=bx[1]; b[1]=b[0]; bx[1]=bx[0]; b[0]=s; bx[0]=id; }
            else if (s > b[1]) { b[3]=b[2]; bx[3]=bx[2]; b[2]=b[1]; bx[2]=bx[1]; b[1]=s; bx[1]=id; }
            else if (s > b[2]) { b[3]=b[2]; bx[3]=bx[2]; b[2]=s; bx[2]=id; }
            else               { b[3]=s; bx[3]=id; }
        }
    }
    #pragma unroll
    for (int k = 0; k < 4; k++) { cs[t * 4 + k] = b[k]; ci[t * 4 + k] = bx[k]; }
    __syncthreads();

    for (int r = 0; r < NRES; r++) {
        float mv = NEG_INF; int mp = 0;
        #pragma unroll
        for (int k = 0; k < 4; k++) {
            float v = cs[t * 4 + k];
            if (v > mv) { mv = v; mp = t * 4 + k; }
        }
        #pragma unroll
        for (int o = 16; o > 0; o >>= 1) {
            float ov = __shfl_down_sync(0xffffffffu, mv, o);
            int   op = __shfl_down_sync(0xffffffffu, mp, o);
            if (ov > mv) { mv = ov; mp = op; }
        }
        if ((t & 31) == 0) { red_s[t >> 5] = mv; red_p[t >> 5] = mp; }
        __syncthreads();
        if (t == 0) {
            float wv = red_s[0]; int wp = red_p[0];
            #pragma unroll
            for (int w = 1; w < 8; w++)
                if (red_s[w] > wv) { wv = red_s[w]; wp = red_p[w]; }
            rix[r] = ci[wp];
            cs[wp] = NEG_INF;
        }
        __syncthreads();
    }

    const int w = t >> 5, l = t & 31;
    for (int c = w; c < NRES; c += 8) {
        int idx = min(max(rix[c], 0), N - 1);
        const float4 cv = __ldg(&((const float4*)corpus)[(size_t)idx * 32 + l]);
        float4 qv = *(const float4*)&qn_s[l * 4];
        float dot = cv.x * qv.x + cv.y * qv.y + cv.z * qv.z + cv.w * qv.w;
        float n2  = cv.x * cv.x + cv.y * cv.y + cv.z * cv.z + cv.w * cv.w;
        #pragma unroll
        for (int o = 16; o > 0; o >>= 1) {
            dot += __shfl_down_sync(0xffffffffu, dot, o);
            n2  += __shfl_down_sync(0xffffffffu, n2,  o);
        }
        if (l == 0) { rs[c] = dot / fmaxf(sqrtf(n2), 1e-12f); rix[c] = idx; }
    }
    __syncthreads();

    if (t < NRES) {
        float s = rs[t]; int id = rix[t];
        int rank = 0;
        for (int jj = 0; jj < NRES; jj++) {
            float so = rs[jj]; int io = rix[jj];
            if (so > s || (so == s && io < id)) rank++;
        }
        if (rank < TOPK) {
            out[q * TOPK + rank]             = s;
            out[NQ * TOPK + q * TOPK + rank] = (float)id;
        }
    }
}

extern "C" void kernel_launch(void* const* d_in, const int* in_sizes, int n_in,
                              void* d_out, int out_size) {
    const float* queries = (const float*)d_in[0];
    const float* corpus  = (const float*)d_in[1];
    int N   = in_sizes[1] / DIM;
    int rpb = (N + NBLK - 1) / NBLK;
    k1_prep<<<1, 1024>>>(queries);
    k2_scan<<<NBLK, TPB>>>(corpus, N, rpb);
    k3_merge<<<NQ, 256>>>(corpus, (float*)d_out, N);
}

// round 15
// speedup vs baseline: 3.1538x; 1.7752x over previous
#include <cuda_runtime.h>
#include <cuda_bf16.h>
#include <math.h>
#include <stdint.h>

#define NQ      32
#define DIM     128
#define TOPK    10
#define NBLK    296                // 2 CTAs/SM, one wave
#define TPB     256                // 8 warps; warp w owns rows [16w,16w+16) of each tile
#define SLOTS   16                 // per (query, block): 8 warps * top-2
#define MCAND   (NBLK * SLOTS)     // 4736 per query
#define NRES    32
#define NEG_INF (-3.402823466e38f)

// ---- static device scratch ----
__device__ float g_qn[NQ * DIM];
__device__ float g_psc[NBLK * NQ * SLOTS];   // encoded scores (row id in low 9 mantissa bits)

__device__ __forceinline__ uint32_t bf2(float lo, float hi) {
    uint32_t d;
    asm("cvt.rn.bf16x2.f32 %0, %1, %2;" : "=r"(d) : "f"(hi), "f"(lo));
    return d;
}
__device__ __forceinline__ void mma16816(float* c, uint32_t a0, uint32_t a1,
                                         uint32_t a2, uint32_t a3,
                                         uint32_t b0, uint32_t b1) {
    asm volatile(
        "mma.sync.aligned.m16n8k16.row.col.f32.bf16.bf16.f32 "
        "{%0,%1,%2,%3}, {%4,%5,%6,%7}, {%8,%9}, {%0,%1,%2,%3};"
        : "+f"(c[0]), "+f"(c[1]), "+f"(c[2]), "+f"(c[3])
        : "r"(a0), "r"(a1), "r"(a2), "r"(a3), "r"(b0), "r"(b1));
}

// ============================================================
// K1: one warp per query — L2-normalize into g_qn
// ============================================================
__global__ void k1_prep(const float* __restrict__ q) {
    const int w = threadIdx.x >> 5;
    const int l = threadIdx.x & 31;
    const float4 v = __ldg(&((const float4*)q)[w * 32 + l]);
    float ss = v.x * v.x + v.y * v.y + v.z * v.z + v.w * v.w;
    #pragma unroll
    for (int o = 16; o > 0; o >>= 1) ss += __shfl_xor_sync(0xffffffffu, ss, o);
    const float inv = 1.f / fmaxf(sqrtf(ss), 1e-12f);
    ((float4*)g_qn)[w * 32 + l] = make_float4(v.x * inv, v.y * inv, v.z * inv, v.w * inv);
}

// ============================================================
// K2: bf16 mma.sync scan — branchless selection, encoded indices,
//     unconditional clamped loads, warp-reduced candidate output.
// ============================================================
__global__ void __launch_bounds__(TPB, 2)
k2_scan(const float* __restrict__ corpus, int N, int rpb) {
    // smQ word(k2, n) at k2*32 + ((n + 8*(k2&3)) & 31); k2 = k/2 in [0,64)
    __shared__ __align__(16) uint32_t smQ[64 * 32];

    const int t    = threadIdx.x;
    const int wrp  = t >> 5;
    const int lane = t & 31;
    const int g    = lane >> 2;     // groupID
    const int tig  = lane & 3;      // threadID_in_group
    const int row0   = blockIdx.x * rpb;
    const int rowEnd = min(row0 + rpb, N);
    const int T = (rowEnd > row0) ? ((rowEnd - row0 + 127) >> 7) : 0;

    // stage B: queries as bf16x2, swizzled
    for (int i = t; i < 64 * 32; i += TPB) {
        int k2 = i >> 5, n = i & 31;
        uint32_t w2 = bf2(g_qn[n * DIM + 2 * k2], g_qn[n * DIM + 2 * k2 + 1]);
        smQ[k2 * 32 + ((n + ((k2 & 3) << 3)) & 31)] = w2;
    }
    __syncthreads();

    uint32_t baddr[8][2];
    #pragma unroll
    for (int kt = 0; kt < 8; kt++) {
        baddr[kt][0] = (uint32_t)((kt * 8 + tig) * 32);
        baddr[kt][1] = (uint32_t)((kt * 8 + tig + 4) * 32);
    }
    const uint32_t nrot = (uint32_t)(g + (tig << 3));

    float m1[16], m2[16];
    #pragma unroll
    for (int s = 0; s < 16; s++) { m1[s] = NEG_INF; m2[s] = NEG_INF; }

    const float2* gc2 = (const float2*)corpus;
    const int lastRow = rowEnd - 1;

    for (int tl = 0; tl < T; tl++) {
        const int rA = row0 + (tl << 7) + wrp * 16 + g;   // row g
        const int rB = rA + 8;                            // row g+8
        const float biasA = (rA < rowEnd) ? 0.f : NEG_INF;
        const float biasB = (rB < rowEnd) ? 0.f : NEG_INF;
        const float2* pA = gc2 + (size_t)min(rA, lastRow) * 64 + tig;
        const float2* pB = gc2 + (size_t)min(rB, lastRow) * 64 + tig;

        float acc[4][4];
        #pragma unroll
        for (int nb = 0; nb < 4; nb++)
            #pragma unroll
            for (int ci = 0; ci < 4; ci++) acc[nb][ci] = 0.f;

        float ss0 = 0.f, ss1 = 0.f;
        #pragma unroll
        for (int kt = 0; kt < 8; kt++) {
            float2 faL = __ldg(pA + kt * 8);
            float2 faH = __ldg(pA + kt * 8 + 4);
            float2 fbL = __ldg(pB + kt * 8);
            float2 fbH = __ldg(pB + kt * 8 + 4);
            ss0 += faL.x * faL.x + faL.y * faL.y + faH.x * faH.x + faH.y * faH.y;
            ss1 += fbL.x * fbL.x + fbL.y * fbL.y + fbH.x * fbH.x + fbH.y * fbH.y;
            uint32_t a0 = bf2(faL.x, faL.y);
            uint32_t a1 = bf2(fbL.x, fbL.y);
            uint32_t a2 = bf2(faH.x, faH.y);
            uint32_t a3 = bf2(fbH.x, fbH.y);
            #pragma unroll
            for (int nb = 0; nb < 4; nb++) {
                uint32_t col = (uint32_t)((nrot + nb * 8) & 31);
                uint32_t b0 = smQ[baddr[kt][0] + col];
                uint32_t b1 = smQ[baddr[kt][1] + col];
                mma16816(acc[nb], a0, a1, a2, a3, b0, b1);
            }
        }
        ss0 += __shfl_xor_sync(0xffffffffu, ss0, 1);
        ss0 += __shfl_xor_sync(0xffffffffu, ss0, 2);
        ss1 += __shfl_xor_sync(0xffffffffu, ss1, 1);
        ss1 += __shfl_xor_sync(0xffffffffu, ss1, 2);
        const float ri0 = rsqrtf(fmaxf(ss0, 1e-24f));
        const float ri1 = rsqrtf(fmaxf(ss1, 1e-24f));
        const uint32_t encBase = ((uint32_t)tl << 4) | ((uint32_t)g << 1);
        #pragma unroll
        for (int nb = 0; nb < 4; nb++) {
            #pragma unroll
            for (int ci = 0; ci < 4; ci++) {
                const int rh = ci >> 1;
                const float ri   = rh ? ri1 : ri0;
                const float bias = rh ? biasB : biasA;
                float sv = fmaf(acc[nb][ci], ri, bias);
                sv = __uint_as_float((__float_as_uint(sv) & ~0x1FFu)
                                     | encBase | (uint32_t)rh);
                const int s = nb * 4 + ci;
                m2[s] = fmaxf(m2[s], fminf(m1[s], sv));   // branchless top-2
                m1[s] = fmaxf(m1[s], sv);
            }
        }
    }

    // ---- warp reduction to top-2 per (query, warp); indices are encoded ----
    // query-slot j in [0,8): nb=j>>1, lsb=j&1 ; merge rh pair, then butterfly over g.
    float M1[8], M2[8];
    #pragma unroll
    for (int j = 0; j < 8; j++) {
        const int nb = j >> 1, lsb = j & 1;
        const int s0 = nb * 4 + lsb;        // rh = 0
        const int s1 = nb * 4 + 2 + lsb;    // rh = 1
        M1[j] = fmaxf(m1[s0], m1[s1]);
        M2[j] = fmaxf(fminf(m1[s0], m1[s1]), fmaxf(m2[s0], m2[s1]));
    }
    #pragma unroll
    for (int step = 4; step <= 16; step <<= 1) {
        #pragma unroll
        for (int j = 0; j < 8; j++) {
            float o1 = __shfl_xor_sync(0xffffffffu, M1[j], step);
            float o2 = __shfl_xor_sync(0xffffffffu, M2[j], step);
            M2[j] = fmaxf(fminf(M1[j], o1), fmaxf(M2[j], o2));
            M1[j] = fmaxf(M1[j], o1);
        }
    }
    if (lane < 4) {
        #pragma unroll
        for (int j = 0; j < 8; j++) {
            const int nb = j >> 1, lsb = j & 1;
            const int q = nb * 8 + lane * 2 + lsb;
            const int base = (blockIdx.x * NQ + q) * SLOTS + wrp * 2;
            g_psc[base]     = M1[j];
            g_psc[base + 1] = M2[j];
        }
    }
}

// ============================================================
// K3: per-query merge (decode rows from mantissa bits) + exact fp32 rescore
// ============================================================
__global__ void __launch_bounds__(256, 1)
k3_merge(const float* __restrict__ corpus, float* __restrict__ out, int N, int rpb) {
    __shared__ float cs[1024];
    __shared__ int   ci[1024];
    __shared__ __align__(16) float qn_s[DIM];
    __shared__ float red_s[8];
    __shared__ int   red_p[8];
    __shared__ float rs[NRES];
    __shared__ int   rix[NRES];

    const int q = blockIdx.x;
    const int t = threadIdx.x;

    if (t < DIM) qn_s[t] = g_qn[q * DIM + t];

    float b[4]  = {NEG_INF, NEG_INF, NEG_INF, NEG_INF};
    int   bx[4] = {0, 0, 0, 0};
    for (int c = t; c < MCAND; c += 256) {
        const int blk = c >> 4, slot = c & 15;
        const float s = g_psc[(blk * NQ + q) * SLOTS + slot];
        if (s > b[3]) {
            const uint32_t bits = __float_as_uint(s);
            const int tl = (int)((bits >> 4) & 31);
            const int gg = (int)((bits >> 1) & 7);
            const int rh = (int)(bits & 1);
            const int wrp = slot >> 1;
            int id = blk * rpb + tl * 128 + wrp * 16 + gg + rh * 8;
            id = min(max(id, 0), N - 1);
            if (s > b[0]) { b[3]=b[2]; bx[3]=bx[2]; b[2]=b[1]; bx[2]=bx[1]; b[1]=b[0]; bx[1]=bx[0]; b[0]=s; bx[0]=id; }
            else if (s > b[1]) { b[3]=b[2]; bx[3]=bx[2]; b[2]=b[1]; bx[2]=bx[1]; b[1]=s; bx[1]=id; }
            else if (s > b[2]) { b[3]=b[2]; bx[3]=bx[2]; b[2]=s; bx[2]=id; }
            else               { b[3]=s; bx[3]=id; }
        }
    }
    #pragma unroll
    for (int k = 0; k < 4; k++) { cs[t * 4 + k] = b[k]; ci[t * 4 + k] = bx[k]; }
    __syncthreads();

    for (int r = 0; r < NRES; r++) {
        float mv = NEG_INF; int mp = 0;
        #pragma unroll
        for (int k = 0; k < 4; k++) {
            float v = cs[t * 4 + k];
            if (v > mv) { mv = v; mp = t * 4 + k; }
        }
        #pragma unroll
        for (int o = 16; o > 0; o >>= 1) {
            float ov = __shfl_down_sync(0xffffffffu, mv, o);
            int   op = __shfl_down_sync(0xffffffffu, mp, o);
            if (ov > mv) { mv = ov; mp = op; }
        }
        if ((t & 31) == 0) { red_s[t >> 5] = mv; red_p[t >> 5] = mp; }
        __syncthreads();
        if (t == 0) {
            float wv = red_s[0]; int wp = red_p[0];
            #pragma unroll
            for (int w = 1; w < 8; w++)
                if (red_s[w] > wv) { wv = red_s[w]; wp = red_p[w]; }
            rix[r] = ci[wp];
            cs[wp] = NEG_INF;
        }
        __syncthreads();
    }

    const int w = t >> 5, l = t & 31;
    for (int c = w; c < NRES; c += 8) {
        const int idx = rix[c];
        const float4 cv = __ldg(&((const float4*)corpus)[(size_t)idx * 32 + l]);
        float4 qv = *(const float4*)&qn_s[l * 4];
        float dot = cv.x * qv.x + cv.y * qv.y + cv.z * qv.z + cv.w * qv.w;
        float n2  = cv.x * cv.x + cv.y * cv.y + cv.z * cv.z + cv.w * cv.w;
        #pragma unroll
        for (int o = 16; o > 0; o >>= 1) {
            dot += __shfl_down_sync(0xffffffffu, dot, o);
            n2  += __shfl_down_sync(0xffffffffu, n2,  o);
        }
        if (l == 0) rs[c] = dot / fmaxf(sqrtf(n2), 1e-12f);
    }
    __syncthreads();

    if (t < NRES) {
        float s = rs[t]; int id = rix[t];
        int rank = 0;
        for (int jj = 0; jj < NRES; jj++) {
            float so = rs[jj]; int io = rix[jj];
            if (so > s || (so == s && io < id)) rank++;
        }
        if (rank < TOPK) {
            out[q * TOPK + rank]             = s;
            out[NQ * TOPK + q * TOPK + rank] = (float)id;
        }
    }
}

extern "C" void kernel_launch(void* const* d_in, const int* in_sizes, int n_in,
                              void* d_out, int out_size) {
    const float* queries = (const float*)d_in[0];
    const float* corpus  = (const float*)d_in[1];
    int N   = in_sizes[1] / DIM;
    int rpb = (N + NBLK - 1) / NBLK;
    k1_prep<<<1, 1024>>>(queries);
    k2_scan<<<NBLK, TPB>>>(corpus, N, rpb);
    k3_merge<<<NQ, 256>>>(corpus, (float*)d_out, N, rpb);
}

// round 16
// speedup vs baseline: 3.1954x; 1.0132x over previous
#include <cuda_runtime.h>
#include <cuda_bf16.h>
#include <math.h>
#include <stdint.h>

#define NQ      32
#define DIM     128
#define TOPK    10
#define NBLK    296                // 2 CTAs/SM, one wave
#define TPB     256                // 8 warps; warp w owns rows [16w,16w+16) of each tile
#define SLOTS   16                 // per (query, block): 8 warps * top-2
#define MCAND   (NBLK * SLOTS)     // 4736 per query
#define NRES    32
#define NEG_INF (-3.402823466e38f)
#define FULLM   0xffffffffu

// ---- static device scratch ----
__device__ float g_psc[NBLK * NQ * SLOTS];   // encoded scores (row id in low 9 mantissa bits)

__device__ __forceinline__ uint32_t bf2(float lo, float hi) {
    uint32_t d;
    asm("cvt.rn.bf16x2.f32 %0, %1, %2;" : "=r"(d) : "f"(hi), "f"(lo));
    return d;
}
__device__ __forceinline__ void mma16816(float* c, uint32_t a0, uint32_t a1,
                                         uint32_t a2, uint32_t a3,
                                         uint32_t b0, uint32_t b1) {
    asm volatile(
        "mma.sync.aligned.m16n8k16.row.col.f32.bf16.bf16.f32 "
        "{%0,%1,%2,%3}, {%4,%5,%6,%7}, {%8,%9}, {%0,%1,%2,%3};"
        : "+f"(c[0]), "+f"(c[1]), "+f"(c[2]), "+f"(c[3])
        : "r"(a0), "r"(a1), "r"(a2), "r"(a3), "r"(b0), "r"(b1));
}

// ============================================================
// K2: bf16 mma.sync scan — fused query prep, float4 A-loads with
//     intra-quad fragment shuffles, LDS.128 B-operands, branchless top-2.
// ============================================================
__global__ void __launch_bounds__(TPB, 2)
k2_scan(const float* __restrict__ corpus, const float* __restrict__ queries,
        int N, int rpb) {
    // smQ word for (k2, n) at: k2*32 + (((n&7) + 2*(k2&3))&7)*4 + (n>>3)
    __shared__ __align__(16) uint32_t smQ[64 * 32];

    const int t    = threadIdx.x;
    const int wrp  = t >> 5;
    const int lane = t & 31;
    const int g    = lane >> 2;     // groupID
    const int tig  = lane & 3;      // threadID_in_group
    const int row0   = blockIdx.x * rpb;
    const int rowEnd = min(row0 + rpb, N);
    const int T = (rowEnd > row0) ? ((rowEnd - row0 + 127) >> 7) : 0;

    // ---- fused query normalize + stage (warp w: queries w, w+8, w+16, w+24) ----
    #pragma unroll
    for (int j = 0; j < 4; j++) {
        const int n = wrp + (j << 3);
        const float4 v = __ldg(&((const float4*)queries)[n * 32 + lane]);
        float ss = v.x * v.x + v.y * v.y + v.z * v.z + v.w * v.w;
        #pragma unroll
        for (int o = 16; o > 0; o >>= 1) ss += __shfl_xor_sync(FULLM, ss, o);
        const float inv = 1.f / fmaxf(sqrtf(ss), 1e-12f);
        const uint32_t w0 = bf2(v.x * inv, v.y * inv);
        const uint32_t w1 = bf2(v.z * inv, v.w * inv);
        const int k2a = 2 * lane, k2b = 2 * lane + 1;
        smQ[k2a * 32 + ((((n & 7) + 2 * (k2a & 3)) & 7) << 2) + (n >> 3)] = w0;
        smQ[k2b * 32 + ((((n & 7) + 2 * (k2b & 3)) & 7) << 2) + (n >> 3)] = w1;
    }
    __syncthreads();

    const uint32_t boff = (uint32_t)(((g + 2 * tig) & 7) << 2);

    float m1[16], m2[16];
    #pragma unroll
    for (int s = 0; s < 16; s++) { m1[s] = NEG_INF; m2[s] = NEG_INF; }

    const float4* gc4 = (const float4*)corpus;
    const int lastRow = rowEnd - 1;
    const int s0 = (g << 2) | (tig >> 1);   // shfl src for word #tig
    const bool odd = (tig & 1);

    for (int tl = 0; tl < T; tl++) {
        const int rA = row0 + (tl << 7) + wrp * 16 + g;   // row g
        const int rB = rA + 8;                            // row g+8
        const float biasA = (rA < rowEnd) ? 0.f : NEG_INF;
        const float biasB = (rB < rowEnd) ? 0.f : NEG_INF;
        const float4* pA = gc4 + (size_t)min(rA, lastRow) * 32 + tig;
        const float4* pB = gc4 + (size_t)min(rB, lastRow) * 32 + tig;

        float acc[4][4];
        #pragma unroll
        for (int nb = 0; nb < 4; nb++)
            #pragma unroll
            for (int ci = 0; ci < 4; ci++) acc[nb][ci] = 0.f;

        float ss0 = 0.f, ss1 = 0.f;
        #pragma unroll
        for (int kt = 0; kt < 8; kt++) {
            const float4 fa = __ldg(pA + kt * 4);
            const float4 fb = __ldg(pB + kt * 4);
            ss0 += fa.x * fa.x + fa.y * fa.y + fa.z * fa.z + fa.w * fa.w;
            ss1 += fb.x * fb.x + fb.y * fb.y + fb.z * fb.z + fb.w * fb.w;
            const uint32_t wa0 = bf2(fa.x, fa.y), wa1 = bf2(fa.z, fa.w);
            const uint32_t wb0 = bf2(fb.x, fb.y), wb1 = bf2(fb.z, fb.w);
            // fragment words: a0/a1 = word #tig (lane s0), a2/a3 = word #(tig+4) (lane s0+2)
            const uint32_t aL  = __shfl_sync(FULLM, wa0, s0);
            const uint32_t aH  = __shfl_sync(FULLM, wa1, s0);
            const uint32_t bL  = __shfl_sync(FULLM, wb0, s0);
            const uint32_t bH  = __shfl_sync(FULLM, wb1, s0);
            const uint32_t aL2 = __shfl_sync(FULLM, wa0, s0 + 2);
            const uint32_t aH2 = __shfl_sync(FULLM, wa1, s0 + 2);
            const uint32_t bL2 = __shfl_sync(FULLM, wb0, s0 + 2);
            const uint32_t bH2 = __shfl_sync(FULLM, wb1, s0 + 2);
            const uint32_t a0 = odd ? aH : aL;
            const uint32_t a1 = odd ? bH : bL;
            const uint32_t a2 = odd ? aH2 : aL2;
            const uint32_t a3 = odd ? bH2 : bL2;
            const int4 bv0 = *(const int4*)&smQ[(uint32_t)((kt * 8 + tig) * 32) + boff];
            const int4 bv1 = *(const int4*)&smQ[(uint32_t)((kt * 8 + tig + 4) * 32) + boff];
            mma16816(acc[0], a0, a1, a2, a3, (uint32_t)bv0.x, (uint32_t)bv1.x);
            mma16816(acc[1], a0, a1, a2, a3, (uint32_t)bv0.y, (uint32_t)bv1.y);
            mma16816(acc[2], a0, a1, a2, a3, (uint32_t)bv0.z, (uint32_t)bv1.z);
            mma16816(acc[3], a0, a1, a2, a3, (uint32_t)bv0.w, (uint32_t)bv1.w);
        }
        ss0 += __shfl_xor_sync(FULLM, ss0, 1);
        ss0 += __shfl_xor_sync(FULLM, ss0, 2);
        ss1 += __shfl_xor_sync(FULLM, ss1, 1);
        ss1 += __shfl_xor_sync(FULLM, ss1, 2);
        const float ri0 = rsqrtf(fmaxf(ss0, 1e-24f));
        const float ri1 = rsqrtf(fmaxf(ss1, 1e-24f));
        const uint32_t encBase = ((uint32_t)tl << 4) | ((uint32_t)g << 1);
        #pragma unroll
        for (int nb = 0; nb < 4; nb++) {
            #pragma unroll
            for (int ci = 0; ci < 4; ci++) {
                const int rh = ci >> 1;
                const float ri   = rh ? ri1 : ri0;
                const float bias = rh ? biasB : biasA;
                float sv = fmaf(acc[nb][ci], ri, bias);
                sv = __uint_as_float((__float_as_uint(sv) & ~0x1FFu)
                                     | encBase | (uint32_t)rh);
                const int s = nb * 4 + ci;
                m2[s] = fmaxf(m2[s], fminf(m1[s], sv));   // branchless top-2
                m1[s] = fmaxf(m1[s], sv);
            }
        }
    }

    // ---- warp reduction to top-2 per (query, warp); indices are encoded ----
    float M1[8], M2[8];
    #pragma unroll
    for (int j = 0; j < 8; j++) {
        const int nb = j >> 1, lsb = j & 1;
        const int sA = nb * 4 + lsb;        // rh = 0
        const int sB = nb * 4 + 2 + lsb;    // rh = 1
        M1[j] = fmaxf(m1[sA], m1[sB]);
        M2[j] = fmaxf(fminf(m1[sA], m1[sB]), fmaxf(m2[sA], m2[sB]));
    }
    #pragma unroll
    for (int step = 4; step <= 16; step <<= 1) {
        #pragma unroll
        for (int j = 0; j < 8; j++) {
            float o1 = __shfl_xor_sync(FULLM, M1[j], step);
            float o2 = __shfl_xor_sync(FULLM, M2[j], step);
            M2[j] = fmaxf(fminf(M1[j], o1), fmaxf(M2[j], o2));
            M1[j] = fmaxf(M1[j], o1);
        }
    }
    if (lane < 4) {
        #pragma unroll
        for (int j = 0; j < 8; j++) {
            const int nb = j >> 1, lsb = j & 1;
            const int q = nb * 8 + lane * 2 + lsb;
            const int base = (blockIdx.x * NQ + q) * SLOTS + wrp * 2;
            g_psc[base]     = M1[j];
            g_psc[base + 1] = M2[j];
        }
    }
}

// ============================================================
// K3: per-query merge (decode rows from mantissa bits) + exact fp32 rescore
// ============================================================
__global__ void __launch_bounds__(256, 1)
k3_merge(const float* __restrict__ corpus, const float* __restrict__ queries,
         float* __restrict__ out, int N, int rpb) {
    __shared__ float cs[1024];
    __shared__ int   ci[1024];
    __shared__ __align__(16) float qn_s[DIM];
    __shared__ float red_s[8];
    __shared__ int   red_p[8];
    __shared__ float rs[NRES];
    __shared__ int   rix[NRES];

    const int q = blockIdx.x;
    const int t = threadIdx.x;

    // warp 0 normalizes this block's query into qn_s
    if (t < 32) {
        const float4 v = __ldg(&((const float4*)queries)[q * 32 + t]);
        float ss = v.x * v.x + v.y * v.y + v.z * v.z + v.w * v.w;
        #pragma unroll
        for (int o = 16; o > 0; o >>= 1) ss += __shfl_xor_sync(FULLM, ss, o);
        const float inv = 1.f / fmaxf(sqrtf(ss), 1e-12f);
        ((float4*)qn_s)[t] = make_float4(v.x * inv, v.y * inv, v.z * inv, v.w * inv);
    }

    float b[4]  = {NEG_INF, NEG_INF, NEG_INF, NEG_INF};
    int   bx[4] = {0, 0, 0, 0};
    for (int c = t; c < MCAND; c += 256) {
        const int blk = c >> 4, slot = c & 15;
        const float s = g_psc[(blk * NQ + q) * SLOTS + slot];
        if (s > b[3]) {
            const uint32_t bits = __float_as_uint(s);
            const int tl = (int)((bits >> 4) & 31);
            const int gg = (int)((bits >> 1) & 7);
            const int rh = (int)(bits & 1);
            const int wrp = slot >> 1;
            int id = blk * rpb + tl * 128 + wrp * 16 + gg + rh * 8;
            id = min(max(id, 0), N - 1);
            if (s > b[0]) { b[3]=b[2]; bx[3]=bx[2]; b[2]=b[1]; bx[2]=bx[1]; b[1]=b[0]; bx[1]=bx[0]; b[0]=s; bx[0]=id; }
            else if (s > b[1]) { b[3]=b[2]; bx[3]=bx[2]; b[2]=b[1]; bx[2]=bx[1]; b[1]=s; bx[1]=id; }
            else if (s > b[2]) { b[3]=b[2]; bx[3]=bx[2]; b[2]=s; bx[2]=id; }
            else               { b[3]=s; bx[3]=id; }
        }
    }
    #pragma unroll
    for (int k = 0; k < 4; k++) { cs[t * 4 + k] = b[k]; ci[t * 4 + k] = bx[k]; }
    __syncthreads();

    for (int r = 0; r < NRES; r++) {
        float mv = NEG_INF; int mp = 0;
        #pragma unroll
        for (int k = 0; k < 4; k++) {
            float v = cs[t * 4 + k];
            if (v > mv) { mv = v; mp = t * 4 + k; }
        }
        #pragma unroll
        for (int o = 16; o > 0; o >>= 1) {
            float ov = __shfl_down_sync(FULLM, mv, o);
            int   op = __shfl_down_sync(FULLM, mp, o);
            if (ov > mv) { mv = ov; mp = op; }
        }
        if ((t & 31) == 0) { red_s[t >> 5] = mv; red_p[t >> 5] = mp; }
        __syncthreads();
        if (t == 0) {
            float wv = red_s[0]; int wp = red_p[0];
            #pragma unroll
            for (int w = 1; w < 8; w++)
                if (red_s[w] > wv) { wv = red_s[w]; wp = red_p[w]; }
            rix[r] = ci[wp];
            cs[wp] = NEG_INF;
        }
        __syncthreads();
    }

    const int w = t >> 5, l = t & 31;
    for (int c = w; c < NRES; c += 8) {
        const int idx = rix[c];
        const float4 cv = __ldg(&((const float4*)corpus)[(size_t)idx * 32 + l]);
        float4 qv = *(const float4*)&qn_s[l * 4];
        float dot = cv.x * qv.x + cv.y * qv.y + cv.z * qv.z + cv.w * qv.w;
        float n2  = cv.x * cv.x + cv.y * cv.y + cv.z * cv.z + cv.w * cv.w;
        #pragma unroll
        for (int o = 16; o > 0; o >>= 1) {
            dot += __shfl_down_sync(FULLM, dot, o);
            n2  += __shfl_down_sync(FULLM, n2,  o);
        }
        if (l == 0) rs[c] = dot / fmaxf(sqrtf(n2), 1e-12f);
    }
    __syncthreads();

    if (t < NRES) {
        float s = rs[t]; int id = rix[t];
        int rank = 0;
        for (int jj = 0; jj < NRES; jj++) {
            float so = rs[jj]; int io = rix[jj];
            if (so > s || (so == s && io < id)) rank++;
        }
        if (rank < TOPK) {
            out[q * TOPK + rank]             = s;
            out[NQ * TOPK + q * TOPK + rank] = (float)id;
        }
    }
}

extern "C" void kernel_launch(void* const* d_in, const int* in_sizes, int n_in,
                              void* d_out, int out_size) {
    const float* queries = (const float*)d_in[0];
    const float* corpus  = (const float*)d_in[1];
    int N   = in_sizes[1] / DIM;
    int rpb = (N + NBLK - 1) / NBLK;
    k2_scan<<<NBLK, TPB>>>(corpus, queries, N, rpb);
    k3_merge<<<NQ, 256>>>(corpus, queries, (float*)d_out, N, rpb);
}